// round 2
// baseline (speedup 1.0000x reference)
#include <cuda_runtime.h>
#include <cuda_bf16.h>
#include <cstddef>

// ---------------------------------------------------------------------------
// Problem constants
//   x:        [8, 256, 64, 64]  (B, C, H, W), HW = 4096
//   groups:   32 (8 channels/group -> 32768 elems per (b,g))
//   time_emb: [8, 1024]
// ---------------------------------------------------------------------------
#define BATCH 8
#define CDIM 256
#define HW 4096
#define TDIM 1024

// Scratch (static device memory; allocation is forbidden)
__device__ float g_bufA[(size_t)BATCH * CDIM * HW];      // 33.5 MB
__device__ float g_bufB[(size_t)BATCH * CDIM * HW];      // 33.5 MB
__device__ float g_qkv [(size_t)BATCH * 3 * CDIM * HW];  // 100.6 MB
__device__ float g_sim [(size_t)BATCH * HW * HW];        // 536 MB
__device__ float g_temb[BATCH * CDIM];

// ---------------------------------------------------------------------------
// GroupNorm (+ optional SiLU). One block per (b, g); 32768 contiguous floats.
// ---------------------------------------------------------------------------
__global__ __launch_bounds__(256) void groupnorm_kernel(
    const float* __restrict__ in, float* __restrict__ out,
    const float* __restrict__ sc, const float* __restrict__ bi, int do_silu)
{
    __shared__ float s_sum[256], s_sq[256];
    __shared__ float s_stats[2];
    const int t = threadIdx.x;
    const int bg = blockIdx.x;                // b*32 + g
    const size_t base = (size_t)bg * 32768;
    const int g = bg & 31;

    float sum = 0.f, sq = 0.f;
    for (int i = t * 4; i < 32768; i += 1024) {
        float4 v = *(const float4*)&in[base + i];
        sum += v.x + v.y + v.z + v.w;
        sq  += v.x*v.x + v.y*v.y + v.z*v.z + v.w*v.w;
    }
    s_sum[t] = sum; s_sq[t] = sq;
    __syncthreads();
    for (int s = 128; s > 0; s >>= 1) {
        if (t < s) { s_sum[t] += s_sum[t + s]; s_sq[t] += s_sq[t + s]; }
        __syncthreads();
    }
    if (t == 0) {
        float mean = s_sum[0] * (1.f / 32768.f);
        float var  = s_sq[0] * (1.f / 32768.f) - mean * mean;
        s_stats[0] = mean;
        s_stats[1] = rsqrtf(var + 1e-5f);
    }
    __syncthreads();
    const float mean = s_stats[0], rstd = s_stats[1];

    for (int i = t * 4; i < 32768; i += 1024) {
        const int c = (g << 3) + (i >> 12);
        const float a = sc[c] * rstd;
        const float b2 = bi[c] - mean * a;
        float4 v = *(const float4*)&in[base + i];
        float4 o;
        o.x = v.x * a + b2; o.y = v.y * a + b2;
        o.z = v.z * a + b2; o.w = v.w * a + b2;
        if (do_silu) {
            o.x = o.x / (1.f + __expf(-o.x));
            o.y = o.y / (1.f + __expf(-o.y));
            o.z = o.z / (1.f + __expf(-o.z));
            o.w = o.w / (1.f + __expf(-o.w));
        }
        *(float4*)&out[base + i] = o;
    }
}

// ---------------------------------------------------------------------------
// time-MLP: temb[b][o] = sum_k silu(te[b][k]) * w[k][o] + mb[o]
// ---------------------------------------------------------------------------
__global__ __launch_bounds__(256) void mlp_kernel(
    const float* __restrict__ te, const float* __restrict__ w,
    const float* __restrict__ mb, float* __restrict__ temb)
{
    __shared__ float s[TDIM];
    const int b = blockIdx.x, t = threadIdx.x;
    for (int i = t; i < TDIM; i += 256) {
        float v = te[b * TDIM + i];
        s[i] = v / (1.f + __expf(-v));
    }
    __syncthreads();
    float acc = 0.f;
    for (int k = 0; k < TDIM; k++) acc = fmaf(s[k], w[k * CDIM + t], acc);
    temb[b * CDIM + t] = acc + mb[t];
}

// ---------------------------------------------------------------------------
// Row softmax over sim: 32768 rows x 4096, in place.
// ---------------------------------------------------------------------------
__global__ __launch_bounds__(256) void softmax_kernel(float* __restrict__ sim)
{
    __shared__ float red[256];
    const int t = threadIdx.x;
    float4* p = (float4*)(sim + (size_t)blockIdx.x * HW);

    float4 v[4];
    float mx = -1e30f;
    #pragma unroll
    for (int j = 0; j < 4; j++) {
        v[j] = p[t + j * 256];
        mx = fmaxf(mx, fmaxf(fmaxf(v[j].x, v[j].y), fmaxf(v[j].z, v[j].w)));
    }
    red[t] = mx; __syncthreads();
    for (int s = 128; s > 0; s >>= 1) {
        if (t < s) red[t] = fmaxf(red[t], red[t + s]);
        __syncthreads();
    }
    mx = red[0];
    __syncthreads();

    float sum = 0.f;
    #pragma unroll
    for (int j = 0; j < 4; j++) {
        v[j].x = __expf(v[j].x - mx); v[j].y = __expf(v[j].y - mx);
        v[j].z = __expf(v[j].z - mx); v[j].w = __expf(v[j].w - mx);
        sum += v[j].x + v[j].y + v[j].z + v[j].w;
    }
    red[t] = sum; __syncthreads();
    for (int s = 128; s > 0; s >>= 1) {
        if (t < s) red[t] += red[t + s];
        __syncthreads();
    }
    const float inv = 1.f / red[0];
    #pragma unroll
    for (int j = 0; j < 4; j++) {
        v[j].x *= inv; v[j].y *= inv; v[j].z *= inv; v[j].w *= inv;
        p[t + j * 256] = v[j];
    }
}

// ---------------------------------------------------------------------------
// Generic batched 128x128x8 SGEMM:  C[m][n] = alpha * sum_k a(k,m)*b(k,n)
//                                              (+ bias[m]) (+ bias2[z*M+m]) (+ res)
// AMODE: 0 = A stored [K][M] (row stride M)     1 = A stored [M][K]
// BMODE: 0 = B stored [K][N]                    1 = B stored [N][K]
//        2 = implicit im2col 3x3 SAME over B = [Cin][64*64], K = Cin*9,
//            k -> (ci = k/9, tap = k%9), matching OIHW weight flattening.
// grid: (N/128, M/128, batch); 256 threads; 8x8 per-thread microtile.
// ---------------------------------------------------------------------------
template<int AMODE, int BMODE>
__global__ __launch_bounds__(256) void gemm_kernel(
    const float* __restrict__ A, const float* __restrict__ B, float* __restrict__ C,
    int M, int N, int K,
    long sA, long sB, long sC,
    float alpha,
    const float* __restrict__ bias,
    const float* __restrict__ bias2,
    const float* __restrict__ res)
{
    __shared__ float As[8][132];
    __shared__ float Bs[8][132];

    const int z = blockIdx.z;
    A += (size_t)z * sA;
    B += (size_t)z * sB;
    C += (size_t)z * sC;
    const float* resp = res ? res + (size_t)z * sC : nullptr;

    const int bm = blockIdx.y * 128, bn = blockIdx.x * 128;
    const int t = threadIdx.x;
    const int tn = t & 15, tm = t >> 4;

    float acc[8][8];
    #pragma unroll
    for (int i = 0; i < 8; i++)
        #pragma unroll
        for (int j = 0; j < 8; j++) acc[i][j] = 0.f;

    for (int k0 = 0; k0 < K; k0 += 8) {
        // ---- stage A tile ----
        if (AMODE == 0) {
            const int k = t >> 5, m = (t & 31) * 4;
            float4 v = *(const float4*)&A[(size_t)(k0 + k) * M + bm + m];
            *(float4*)&As[k][m] = v;
        } else {
            const int m = t >> 1, k = (t & 1) * 4;
            float4 v = *(const float4*)&A[(size_t)(bm + m) * K + k0 + k];
            As[k + 0][m] = v.x; As[k + 1][m] = v.y;
            As[k + 2][m] = v.z; As[k + 3][m] = v.w;
        }
        // ---- stage B tile ----
        if (BMODE == 0) {
            const int k = t >> 5, n = (t & 31) * 4;
            float4 v = *(const float4*)&B[(size_t)(k0 + k) * N + bn + n];
            *(float4*)&Bs[k][n] = v;
        } else if (BMODE == 1) {
            const int n = t >> 1, k = (t & 1) * 4;
            float4 v = *(const float4*)&B[(size_t)(bn + n) * K + k0 + k];
            Bs[k + 0][n] = v.x; Bs[k + 1][n] = v.y;
            Bs[k + 2][n] = v.z; Bs[k + 3][n] = v.w;
        } else {
            const int k = t >> 5, n0 = (t & 31) * 4;
            const int kk = k0 + k;
            const int ci = kk / 9;
            const int tap = kk - ci * 9;
            const int dy = tap / 3 - 1, dx = tap - (tap / 3) * 3 - 1;
            const float* Bc = B + (size_t)ci * HW;
            #pragma unroll
            for (int j = 0; j < 4; j++) {
                const int nn = bn + n0 + j;
                const int y = (nn >> 6) + dy, x = (nn & 63) + dx;
                float v = 0.f;
                if ((unsigned)x < 64u && (unsigned)y < 64u) v = Bc[y * 64 + x];
                Bs[k][n0 + j] = v;
            }
        }
        __syncthreads();

        #pragma unroll
        for (int kk = 0; kk < 8; kk++) {
            float4 a0 = *(const float4*)&As[kk][tm * 4];
            float4 a1 = *(const float4*)&As[kk][tm * 4 + 64];
            float4 b0 = *(const float4*)&Bs[kk][tn * 4];
            float4 b1 = *(const float4*)&Bs[kk][tn * 4 + 64];
            float av[8] = {a0.x, a0.y, a0.z, a0.w, a1.x, a1.y, a1.z, a1.w};
            float bv[8] = {b0.x, b0.y, b0.z, b0.w, b1.x, b1.y, b1.z, b1.w};
            #pragma unroll
            for (int i = 0; i < 8; i++)
                #pragma unroll
                for (int j = 0; j < 8; j++)
                    acc[i][j] = fmaf(av[i], bv[j], acc[i][j]);
        }
        __syncthreads();
    }

    // ---- epilogue ----
    #pragma unroll
    for (int i = 0; i < 8; i++) {
        const int ml = (i < 4) ? (tm * 4 + i) : (tm * 4 + 64 + (i - 4));
        const int m = bm + ml;
        float badd = 0.f;
        if (bias)  badd += bias[m];
        if (bias2) badd += bias2[z * M + m];
        #pragma unroll
        for (int jg = 0; jg < 2; jg++) {
            const int n = bn + tn * 4 + jg * 64;
            const size_t off = (size_t)m * N + n;
            float4 o;
            o.x = acc[i][jg * 4 + 0] * alpha + badd;
            o.y = acc[i][jg * 4 + 1] * alpha + badd;
            o.z = acc[i][jg * 4 + 2] * alpha + badd;
            o.w = acc[i][jg * 4 + 3] * alpha + badd;
            if (resp) {
                float4 r = *(const float4*)&resp[off];
                o.x += r.x; o.y += r.y; o.z += r.z; o.w += r.w;
            }
            *(float4*)&C[off] = o;
        }
    }
}

// ---------------------------------------------------------------------------
// Launch
// ---------------------------------------------------------------------------
extern "C" void kernel_launch(void* const* d_in, const int* in_sizes, int n_in,
                              void* d_out, int out_size)
{
    const float* x        = (const float*)d_in[0];
    const float* time_emb = (const float*)d_in[1];
    const float* gn1_s    = (const float*)d_in[2];
    const float* gn1_b    = (const float*)d_in[3];
    const float* conv1_w  = (const float*)d_in[4];
    const float* conv1_b  = (const float*)d_in[5];
    const float* mlp_w    = (const float*)d_in[6];
    const float* mlp_b    = (const float*)d_in[7];
    const float* gn2_s    = (const float*)d_in[8];
    const float* gn2_b    = (const float*)d_in[9];
    const float* conv2_w  = (const float*)d_in[10];
    const float* conv2_b  = (const float*)d_in[11];
    const float* an_s     = (const float*)d_in[12];
    const float* an_b     = (const float*)d_in[13];
    const float* qkv_w    = (const float*)d_in[14];
    const float* qkv_b    = (const float*)d_in[15];
    const float* out_w    = (const float*)d_in[16];
    const float* out_b    = (const float*)d_in[17];
    float* out = (float*)d_out;

    // Resolve all static scratch up front (non-stream-ordered queries; legal
    // under graph capture).
    float *bufA = nullptr, *bufB = nullptr, *qkvb = nullptr,
          *sim = nullptr, *temb = nullptr;
    cudaGetSymbolAddress((void**)&bufA, g_bufA);
    cudaGetSymbolAddress((void**)&bufB, g_bufB);
    cudaGetSymbolAddress((void**)&qkvb, g_qkv);
    cudaGetSymbolAddress((void**)&sim,  g_sim);
    cudaGetSymbolAddress((void**)&temb, g_temb);

    const long sAct = (long)CDIM * HW;        // 256*4096 per-batch activation stride
    const long sQkv = (long)3 * CDIM * HW;    // 768*4096
    const long sSim = (long)HW * HW;          // 4096*4096

    // temb = silu(time_emb) @ mlp_w + mlp_b
    mlp_kernel<<<BATCH, 256>>>(time_emb, mlp_w, mlp_b, temb);

    // t1 = silu(gn1(x))
    groupnorm_kernel<<<BATCH * 32, 256>>>(x, bufA, gn1_s, gn1_b, 1);

    // h1 = conv1(t1) + conv1_b + temb          (implicit-im2col GEMM)
    gemm_kernel<1, 2><<<dim3(32, 2, BATCH), 256>>>(
        conv1_w, bufA, bufB, CDIM, HW, CDIM * 9,
        0L, sAct, sAct, 1.f, conv1_b, temb, nullptr);

    // t2 = silu(gn2(h1))
    groupnorm_kernel<<<BATCH * 32, 256>>>(bufB, bufA, gn2_s, gn2_b, 1);

    // xr = conv2(t2) + conv2_b + x
    gemm_kernel<1, 2><<<dim3(32, 2, BATCH), 256>>>(
        conv2_w, bufA, bufB, CDIM, HW, CDIM * 9,
        0L, sAct, sAct, 1.f, conv2_b, nullptr, x);

    // a = gn_an(xr)          (no silu)
    groupnorm_kernel<<<BATCH * 32, 256>>>(bufB, bufA, an_s, an_b, 0);

    // qkv = W_qkv @ a + qkv_b        [b][768][4096]
    gemm_kernel<1, 0><<<dim3(32, 6, BATCH), 256>>>(
        qkv_w, bufA, qkvb, 3 * CDIM, HW, CDIM,
        0L, sAct, sQkv, 1.f, qkv_b, nullptr, nullptr);

    // sim = (Q^T K) * C^-0.5          [b][4096][4096]
    gemm_kernel<0, 0><<<dim3(32, 32, BATCH), 256>>>(
        qkvb, qkvb + (size_t)CDIM * HW, sim, HW, HW, CDIM,
        sQkv, sQkv, sSim, 0.0625f, nullptr, nullptr, nullptr);

    // softmax rows
    softmax_kernel<<<BATCH * HW, 256>>>(sim);

    // o[c][i] = sum_j V[c][j] * attn[i][j]     -> bufA
    gemm_kernel<1, 1><<<dim3(32, 2, BATCH), 256>>>(
        qkvb + (size_t)2 * CDIM * HW, sim, bufA, CDIM, HW, HW,
        sQkv, sSim, sAct, 1.f, nullptr, nullptr, nullptr);

    // out = W_out @ o + out_b + xr
    gemm_kernel<1, 0><<<dim3(32, 2, BATCH), 256>>>(
        out_w, bufA, out, CDIM, HW, CDIM,
        0L, sAct, sAct, 1.f, out_b, nullptr, bufB);
}

// round 4
// speedup vs baseline: 1.7435x; 1.7435x over previous
#include <cuda_runtime.h>
#include <cuda_bf16.h>
#include <cstdint>
#include <cstddef>

#define BATCH 8
#define CDIM 256
#define HW 4096
#define TDIM 1024

// ---------------------------------------------------------------------------
// Static scratch (allocation forbidden)
// ---------------------------------------------------------------------------
__device__ float g_bufA[(size_t)BATCH * CDIM * HW];                  // 33.5 MB
__device__ float g_bufB[(size_t)BATCH * CDIM * HW];                  // 33.5 MB
__device__ float g_qkv [(size_t)BATCH * 3 * CDIM * HW];              // 100.6 MB
__device__ float g_sim [(size_t)BATCH * HW * HW];                    // 536 MB
__device__ float g_temb[BATCH * CDIM];
__device__ __nv_bfloat16 g_qT  [(size_t)BATCH * HW * CDIM];          // 16.8 MB
__device__ __nv_bfloat16 g_kT  [(size_t)BATCH * HW * CDIM];          // 16.8 MB
__device__ __nv_bfloat16 g_vbf [(size_t)BATCH * CDIM * HW];          // 16.8 MB
__device__ __nv_bfloat16 g_attn[(size_t)BATCH * HW * HW];            // 268 MB

// ---------------------------------------------------------------------------
// PTX helpers (sm_80+ path: cp.async / ldmatrix / mma.sync — valid on sm_100)
// ---------------------------------------------------------------------------
__device__ __forceinline__ uint32_t smem_u32(const void* p) {
    uint32_t a;
    asm("{ .reg .u64 t; cvta.to.shared.u64 t, %1; cvt.u32.u64 %0, t; }"
        : "=r"(a) : "l"(p));
    return a;
}
__device__ __forceinline__ void cp16(uint32_t dst, const void* src) {
    asm volatile("cp.async.cg.shared.global [%0], [%1], 16;" :: "r"(dst), "l"(src));
}
#define CP_COMMIT() asm volatile("cp.async.commit_group;" ::: "memory")
#define CP_WAIT(n)  asm volatile("cp.async.wait_group %0;" :: "n"(n) : "memory")

__device__ __forceinline__ void ldsm4(uint32_t& r0, uint32_t& r1,
                                      uint32_t& r2, uint32_t& r3, uint32_t addr) {
    asm volatile("ldmatrix.sync.aligned.m8n8.x4.shared.b16 {%0,%1,%2,%3}, [%4];"
                 : "=r"(r0), "=r"(r1), "=r"(r2), "=r"(r3) : "r"(addr));
}
__device__ __forceinline__ void mma16816(float* c, const uint32_t* a,
                                         uint32_t b0, uint32_t b1) {
    asm volatile(
        "mma.sync.aligned.m16n8k16.row.col.f32.bf16.bf16.f32 "
        "{%0,%1,%2,%3}, {%4,%5,%6,%7}, {%8,%9}, {%0,%1,%2,%3};"
        : "+f"(c[0]), "+f"(c[1]), "+f"(c[2]), "+f"(c[3])
        : "r"(a[0]), "r"(a[1]), "r"(a[2]), "r"(a[3]), "r"(b0), "r"(b1));
}

// ---------------------------------------------------------------------------
// bf16 tensor-core GEMM: C[m][n] = alpha * sum_k A[m][k] * B[n][k]
// A: [Mtot][K] bf16 K-major; B: [Ntot][K] bf16 K-major; C: fp32, ld = 4096.
// CTA tile 128x128, BK=32, cp.async double buffer, 8 warps (4m x 2n),
// warp tile 32x64 (2 x 8 m16n8k16). Smem rows padded to 80B: ldmatrix bank
// stride 20 mod 32 -> conflict-free.
// grid (Ntot/128, Mtot/128, BATCH), 256 threads.
// ---------------------------------------------------------------------------
#define MMA_STAGE 20480   // A: 128*80 + B: 128*80

__device__ __forceinline__ void mma_load_stage(
    uint32_t sbase, const __nv_bfloat16* __restrict__ A,
    const __nv_bfloat16* __restrict__ B, int K, int k0, int tid)
{
    #pragma unroll
    for (int h = 0; h < 2; h++) {
        const int c = tid + h * 256;          // 0..511
        const int r = c >> 2, sub = c & 3;
        cp16(sbase + r * 80 + sub * 16, A + (size_t)r * K + k0 + sub * 8);
        cp16(sbase + 10240 + r * 80 + sub * 16, B + (size_t)r * K + k0 + sub * 8);
    }
}

__global__ __launch_bounds__(256, 2) void mma_gemm_kernel(
    const __nv_bfloat16* __restrict__ A, const __nv_bfloat16* __restrict__ B,
    float* __restrict__ C, int K, long sA, long sB, long sC, float alpha)
{
    __shared__ __align__(128) char smem[2 * MMA_STAGE];
    const uint32_t sb = smem_u32(smem);
    const int tid = threadIdx.x;
    const int wid = tid >> 5, lane = tid & 31;
    const int wm = wid & 3, wn = wid >> 2;
    const int z = blockIdx.z;
    const int bm = blockIdx.y * 128, bn = blockIdx.x * 128;
    A += (size_t)z * sA + (size_t)bm * K;
    B += (size_t)z * sB + (size_t)bn * K;
    C += (size_t)z * sC;

    float acc[2][8][4];
    #pragma unroll
    for (int mt = 0; mt < 2; mt++)
        #pragma unroll
        for (int nt = 0; nt < 8; nt++)
            #pragma unroll
            for (int e = 0; e < 4; e++) acc[mt][nt][e] = 0.f;

    const int NC = K >> 5;
    mma_load_stage(sb, A, B, K, 0, tid);
    CP_COMMIT();

    // precomputed ldmatrix lane addressing
    const int a_r  = lane & 15;
    const int a_kc = (lane >> 4) << 3;
    const int b_r  = (lane & 7) + ((lane >> 4) << 3);
    const int b_kc = ((lane >> 3) & 1) << 3;

    for (int c = 0; c < NC; c++) {
        if (c + 1 < NC) {
            mma_load_stage(sb + ((c + 1) & 1) * MMA_STAGE, A, B, K, (c + 1) << 5, tid);
            CP_COMMIT();
            CP_WAIT(1);
        } else {
            CP_WAIT(0);
        }
        __syncthreads();

        const uint32_t stA = sb + (c & 1) * MMA_STAGE;
        const uint32_t stB = stA + 10240;
        #pragma unroll
        for (int kk = 0; kk < 32; kk += 16) {
            uint32_t a[2][4];
            #pragma unroll
            for (int mt = 0; mt < 2; mt++) {
                const int r = wm * 32 + mt * 16 + a_r;
                ldsm4(a[mt][0], a[mt][1], a[mt][2], a[mt][3],
                      stA + r * 80 + (kk + a_kc) * 2);
            }
            uint32_t b[8][2];
            #pragma unroll
            for (int p = 0; p < 4; p++) {
                const int nr = wn * 64 + p * 16 + b_r;
                ldsm4(b[p * 2][0], b[p * 2][1], b[p * 2 + 1][0], b[p * 2 + 1][1],
                      stB + nr * 80 + (kk + b_kc) * 2);
            }
            #pragma unroll
            for (int mt = 0; mt < 2; mt++)
                #pragma unroll
                for (int nt = 0; nt < 8; nt++)
                    mma16816(acc[mt][nt], a[mt], b[nt][0], b[nt][1]);
        }
        __syncthreads();
    }

    // epilogue: acc layout m16n8: rows t/4 and t/4+8, cols (t%4)*2, +1
    #pragma unroll
    for (int mt = 0; mt < 2; mt++) {
        const int row0 = bm + wm * 32 + mt * 16 + (lane >> 2);
        #pragma unroll
        for (int nt = 0; nt < 8; nt++) {
            const int col = bn + wn * 64 + nt * 8 + (lane & 3) * 2;
            float2 v0 = { acc[mt][nt][0] * alpha, acc[mt][nt][1] * alpha };
            float2 v1 = { acc[mt][nt][2] * alpha, acc[mt][nt][3] * alpha };
            *(float2*)(C + (size_t)row0 * 4096 + col) = v0;
            *(float2*)(C + (size_t)(row0 + 8) * 4096 + col) = v1;
        }
    }
}

// ---------------------------------------------------------------------------
// Transpose+convert: q,k fp32 [C][HW] -> bf16 [HW][C]
// ---------------------------------------------------------------------------
__global__ __launch_bounds__(256) void transpose_cvt_kernel(
    const float* __restrict__ qkv, __nv_bfloat16* __restrict__ qT,
    __nv_bfloat16* __restrict__ kT)
{
    __shared__ float tile[32][33];
    const int b = blockIdx.z >> 1, which = blockIdx.z & 1;
    const float* s = qkv + (size_t)b * (3 * CDIM * HW)
                   + (size_t)(which * CDIM + blockIdx.y * 32) * HW + blockIdx.x * 32;
    __nv_bfloat16* d = (which ? kT : qT) + (size_t)b * HW * CDIM
                     + (size_t)(blockIdx.x * 32) * CDIM + blockIdx.y * 32;
    const int tx = threadIdx.x & 31, ty = threadIdx.x >> 5;
    #pragma unroll
    for (int r = 0; r < 32; r += 8)
        tile[ty + r][tx] = s[(size_t)(ty + r) * HW + tx];
    __syncthreads();
    #pragma unroll
    for (int r = 0; r < 32; r += 8)
        d[(size_t)(ty + r) * CDIM + tx] = __float2bfloat16(tile[tx][ty + r]);
}

// v fp32 [C][HW] -> bf16 [C][HW]
__global__ __launch_bounds__(256) void cvt_v_kernel(
    const float* __restrict__ qkv, __nv_bfloat16* __restrict__ v)
{
    const size_t i = (size_t)blockIdx.x * 1024 + threadIdx.x * 4;
    const size_t z = blockIdx.y;
    float4 f = *(const float4*)(qkv + z * (size_t)(3 * CDIM * HW)
                                + (size_t)2 * CDIM * HW + i);
    __nv_bfloat162 lo = __floats2bfloat162_rn(f.x, f.y);
    __nv_bfloat162 hi = __floats2bfloat162_rn(f.z, f.w);
    uint2 o = { *(uint32_t*)&lo, *(uint32_t*)&hi };
    *(uint2*)(v + z * (size_t)(CDIM * HW) + i) = o;
}

// ---------------------------------------------------------------------------
// GroupNorm (+ optional SiLU)
// ---------------------------------------------------------------------------
__global__ __launch_bounds__(256) void groupnorm_kernel(
    const float* __restrict__ in, float* __restrict__ out,
    const float* __restrict__ sc, const float* __restrict__ bi, int do_silu)
{
    __shared__ float s_sum[256], s_sq[256];
    __shared__ float s_stats[2];
    const int t = threadIdx.x;
    const int bg = blockIdx.x;
    const size_t base = (size_t)bg * 32768;
    const int g = bg & 31;

    float sum = 0.f, sq = 0.f;
    for (int i = t * 4; i < 32768; i += 1024) {
        float4 v = *(const float4*)&in[base + i];
        sum += v.x + v.y + v.z + v.w;
        sq  += v.x*v.x + v.y*v.y + v.z*v.z + v.w*v.w;
    }
    s_sum[t] = sum; s_sq[t] = sq;
    __syncthreads();
    for (int s = 128; s > 0; s >>= 1) {
        if (t < s) { s_sum[t] += s_sum[t + s]; s_sq[t] += s_sq[t + s]; }
        __syncthreads();
    }
    if (t == 0) {
        float mean = s_sum[0] * (1.f / 32768.f);
        float var  = s_sq[0] * (1.f / 32768.f) - mean * mean;
        s_stats[0] = mean;
        s_stats[1] = rsqrtf(var + 1e-5f);
    }
    __syncthreads();
    const float mean = s_stats[0], rstd = s_stats[1];

    for (int i = t * 4; i < 32768; i += 1024) {
        const int c = (g << 3) + (i >> 12);
        const float a = sc[c] * rstd;
        const float b2 = bi[c] - mean * a;
        float4 v = *(const float4*)&in[base + i];
        float4 o;
        o.x = v.x * a + b2; o.y = v.y * a + b2;
        o.z = v.z * a + b2; o.w = v.w * a + b2;
        if (do_silu) {
            o.x = o.x / (1.f + __expf(-o.x));
            o.y = o.y / (1.f + __expf(-o.y));
            o.z = o.z / (1.f + __expf(-o.z));
            o.w = o.w / (1.f + __expf(-o.w));
        }
        *(float4*)&out[base + i] = o;
    }
}

// ---------------------------------------------------------------------------
// time-MLP
// ---------------------------------------------------------------------------
__global__ __launch_bounds__(256) void mlp_kernel(
    const float* __restrict__ te, const float* __restrict__ w,
    const float* __restrict__ mb, float* __restrict__ temb)
{
    __shared__ float s[TDIM];
    const int b = blockIdx.x, t = threadIdx.x;
    for (int i = t; i < TDIM; i += 256) {
        float v = te[b * TDIM + i];
        s[i] = v / (1.f + __expf(-v));
    }
    __syncthreads();
    float acc = 0.f;
    for (int k = 0; k < TDIM; k++) acc = fmaf(s[k], w[k * CDIM + t], acc);
    temb[b * CDIM + t] = acc + mb[t];
}

// ---------------------------------------------------------------------------
// Row softmax: fp32 sim in, bf16 attn out. One block per row.
// ---------------------------------------------------------------------------
__global__ __launch_bounds__(256) void softmax_kernel(
    const float* __restrict__ sim, __nv_bfloat16* __restrict__ attn)
{
    __shared__ float red[256];
    const int t = threadIdx.x;
    const float4* p = (const float4*)(sim + (size_t)blockIdx.x * HW);
    __nv_bfloat16* arow = attn + (size_t)blockIdx.x * HW;

    float4 v[4];
    float mx = -1e30f;
    #pragma unroll
    for (int j = 0; j < 4; j++) {
        v[j] = p[t + j * 256];
        mx = fmaxf(mx, fmaxf(fmaxf(v[j].x, v[j].y), fmaxf(v[j].z, v[j].w)));
    }
    red[t] = mx; __syncthreads();
    for (int s = 128; s > 0; s >>= 1) {
        if (t < s) red[t] = fmaxf(red[t], red[t + s]);
        __syncthreads();
    }
    mx = red[0];
    __syncthreads();

    float sum = 0.f;
    #pragma unroll
    for (int j = 0; j < 4; j++) {
        v[j].x = __expf(v[j].x - mx); v[j].y = __expf(v[j].y - mx);
        v[j].z = __expf(v[j].z - mx); v[j].w = __expf(v[j].w - mx);
        sum += v[j].x + v[j].y + v[j].z + v[j].w;
    }
    red[t] = sum; __syncthreads();
    for (int s = 128; s > 0; s >>= 1) {
        if (t < s) red[t] += red[t + s];
        __syncthreads();
    }
    const float inv = 1.f / red[0];
    #pragma unroll
    for (int j = 0; j < 4; j++) {
        __nv_bfloat162 lo = __floats2bfloat162_rn(v[j].x * inv, v[j].y * inv);
        __nv_bfloat162 hi = __floats2bfloat162_rn(v[j].z * inv, v[j].w * inv);
        uint2 o = { *(uint32_t*)&lo, *(uint32_t*)&hi };
        *(uint2*)(arow + (size_t)(t + j * 256) * 4) = o;
    }
}

// ---------------------------------------------------------------------------
// SIMT SGEMM (convs / qkv / out)
// ---------------------------------------------------------------------------
template<int AMODE, int BMODE>
__global__ __launch_bounds__(256) void gemm_kernel(
    const float* __restrict__ A, const float* __restrict__ B, float* __restrict__ C,
    int M, int N, int K,
    long sA, long sB, long sC,
    float alpha,
    const float* __restrict__ bias,
    const float* __restrict__ bias2,
    const float* __restrict__ res)
{
    __shared__ float As[8][132];
    __shared__ float Bs[8][132];

    const int z = blockIdx.z;
    A += (size_t)z * sA;
    B += (size_t)z * sB;
    C += (size_t)z * sC;
    const float* resp = res ? res + (size_t)z * sC : nullptr;

    const int bm = blockIdx.y * 128, bn = blockIdx.x * 128;
    const int t = threadIdx.x;
    const int tn = t & 15, tm = t >> 4;

    float acc[8][8];
    #pragma unroll
    for (int i = 0; i < 8; i++)
        #pragma unroll
        for (int j = 0; j < 8; j++) acc[i][j] = 0.f;

    for (int k0 = 0; k0 < K; k0 += 8) {
        if (AMODE == 0) {
            const int k = t >> 5, m = (t & 31) * 4;
            float4 v = *(const float4*)&A[(size_t)(k0 + k) * M + bm + m];
            *(float4*)&As[k][m] = v;
        } else {
            const int m = t >> 1, k = (t & 1) * 4;
            float4 v = *(const float4*)&A[(size_t)(bm + m) * K + k0 + k];
            As[k + 0][m] = v.x; As[k + 1][m] = v.y;
            As[k + 2][m] = v.z; As[k + 3][m] = v.w;
        }
        if (BMODE == 0) {
            const int k = t >> 5, n = (t & 31) * 4;
            float4 v = *(const float4*)&B[(size_t)(k0 + k) * N + bn + n];
            *(float4*)&Bs[k][n] = v;
        } else if (BMODE == 1) {
            const int n = t >> 1, k = (t & 1) * 4;
            float4 v = *(const float4*)&B[(size_t)(bn + n) * K + k0 + k];
            Bs[k + 0][n] = v.x; Bs[k + 1][n] = v.y;
            Bs[k + 2][n] = v.z; Bs[k + 3][n] = v.w;
        } else {
            const int k = t >> 5, n0 = (t & 31) * 4;
            const int kk = k0 + k;
            const int ci = kk / 9;
            const int tap = kk - ci * 9;
            const int dy = tap / 3 - 1, dx = tap - (tap / 3) * 3 - 1;
            const float* Bc = B + (size_t)ci * HW;
            #pragma unroll
            for (int j = 0; j < 4; j++) {
                const int nn = bn + n0 + j;
                const int y = (nn >> 6) + dy, x = (nn & 63) + dx;
                float v = 0.f;
                if ((unsigned)x < 64u && (unsigned)y < 64u) v = Bc[y * 64 + x];
                Bs[k][n0 + j] = v;
            }
        }
        __syncthreads();

        #pragma unroll
        for (int kk = 0; kk < 8; kk++) {
            float4 a0 = *(const float4*)&As[kk][tm * 4];
            float4 a1 = *(const float4*)&As[kk][tm * 4 + 64];
            float4 b0 = *(const float4*)&Bs[kk][tn * 4];
            float4 b1 = *(const float4*)&Bs[kk][tn * 4 + 64];
            float av[8] = {a0.x, a0.y, a0.z, a0.w, a1.x, a1.y, a1.z, a1.w};
            float bv[8] = {b0.x, b0.y, b0.z, b0.w, b1.x, b1.y, b1.z, b1.w};
            #pragma unroll
            for (int i = 0; i < 8; i++)
                #pragma unroll
                for (int j = 0; j < 8; j++)
                    acc[i][j] = fmaf(av[i], bv[j], acc[i][j]);
        }
        __syncthreads();
    }

    #pragma unroll
    for (int i = 0; i < 8; i++) {
        const int ml = (i < 4) ? (tm * 4 + i) : (tm * 4 + 64 + (i - 4));
        const int m = bm + ml;
        float badd = 0.f;
        if (bias)  badd += bias[m];
        if (bias2) badd += bias2[z * M + m];
        #pragma unroll
        for (int jg = 0; jg < 2; jg++) {
            const int n = bn + tn * 4 + jg * 64;
            const size_t off = (size_t)m * N + n;
            float4 o;
            o.x = acc[i][jg * 4 + 0] * alpha + badd;
            o.y = acc[i][jg * 4 + 1] * alpha + badd;
            o.z = acc[i][jg * 4 + 2] * alpha + badd;
            o.w = acc[i][jg * 4 + 3] * alpha + badd;
            if (resp) {
                float4 r = *(const float4*)&resp[off];
                o.x += r.x; o.y += r.y; o.z += r.z; o.w += r.w;
            }
            *(float4*)&C[off] = o;
        }
    }
}

// ---------------------------------------------------------------------------
// Launch
// ---------------------------------------------------------------------------
extern "C" void kernel_launch(void* const* d_in, const int* in_sizes, int n_in,
                              void* d_out, int out_size)
{
    const float* x        = (const float*)d_in[0];
    const float* time_emb = (const float*)d_in[1];
    const float* gn1_s    = (const float*)d_in[2];
    const float* gn1_b    = (const float*)d_in[3];
    const float* conv1_w  = (const float*)d_in[4];
    const float* conv1_b  = (const float*)d_in[5];
    const float* mlp_w    = (const float*)d_in[6];
    const float* mlp_b    = (const float*)d_in[7];
    const float* gn2_s    = (const float*)d_in[8];
    const float* gn2_b    = (const float*)d_in[9];
    const float* conv2_w  = (const float*)d_in[10];
    const float* conv2_b  = (const float*)d_in[11];
    const float* an_s     = (const float*)d_in[12];
    const float* an_b     = (const float*)d_in[13];
    const float* qkv_w    = (const float*)d_in[14];
    const float* qkv_b    = (const float*)d_in[15];
    const float* out_w    = (const float*)d_in[16];
    const float* out_b    = (const float*)d_in[17];
    float* out = (float*)d_out;

    float *bufA, *bufB, *qkvb, *sim, *temb;
    __nv_bfloat16 *qT, *kT, *vbf, *attn;
    cudaGetSymbolAddress((void**)&bufA, g_bufA);
    cudaGetSymbolAddress((void**)&bufB, g_bufB);
    cudaGetSymbolAddress((void**)&qkvb, g_qkv);
    cudaGetSymbolAddress((void**)&sim,  g_sim);
    cudaGetSymbolAddress((void**)&temb, g_temb);
    cudaGetSymbolAddress((void**)&qT,   g_qT);
    cudaGetSymbolAddress((void**)&kT,   g_kT);
    cudaGetSymbolAddress((void**)&vbf,  g_vbf);
    cudaGetSymbolAddress((void**)&attn, g_attn);

    const long sAct = (long)CDIM * HW;
    const long sQkv = (long)3 * CDIM * HW;
    const long sSim = (long)HW * HW;

    mlp_kernel<<<BATCH, 256>>>(time_emb, mlp_w, mlp_b, temb);
    groupnorm_kernel<<<BATCH * 32, 256>>>(x, bufA, gn1_s, gn1_b, 1);
    gemm_kernel<1, 2><<<dim3(32, 2, BATCH), 256>>>(
        conv1_w, bufA, bufB, CDIM, HW, CDIM * 9,
        0L, sAct, sAct, 1.f, conv1_b, temb, nullptr);
    groupnorm_kernel<<<BATCH * 32, 256>>>(bufB, bufA, gn2_s, gn2_b, 1);
    gemm_kernel<1, 2><<<dim3(32, 2, BATCH), 256>>>(
        conv2_w, bufA, bufB, CDIM, HW, CDIM * 9,
        0L, sAct, sAct, 1.f, conv2_b, nullptr, x);
    groupnorm_kernel<<<BATCH * 32, 256>>>(bufB, bufA, an_s, an_b, 0);
    gemm_kernel<1, 0><<<dim3(32, 6, BATCH), 256>>>(
        qkv_w, bufA, qkvb, 3 * CDIM, HW, CDIM,
        0L, sAct, sQkv, 1.f, qkv_b, nullptr, nullptr);

    // bf16 prep for attention
    transpose_cvt_kernel<<<dim3(HW / 32, CDIM / 32, BATCH * 2), 256>>>(qkvb, qT, kT);
    cvt_v_kernel<<<dim3(1024, BATCH), 256>>>(qkvb, vbf);

    // sim = (Q^T K) * C^-0.5   [mma.sync bf16]
    mma_gemm_kernel<<<dim3(32, 32, BATCH), 256>>>(
        qT, kT, sim, CDIM, (long)HW * CDIM, (long)HW * CDIM, sSim, 0.0625f);

    // softmax -> bf16 attn
    softmax_kernel<<<BATCH * HW, 256>>>(sim, attn);

    // o = V attn^T   [mma.sync bf16]  -> bufA fp32 [C][HW]
    mma_gemm_kernel<<<dim3(32, 2, BATCH), 256>>>(
        vbf, attn, bufA, HW, sAct, sSim, sAct, 1.f);

    // out = W_out @ o + out_b + xr
    gemm_kernel<1, 0><<<dim3(32, 2, BATCH), 256>>>(
        out_w, bufA, out, CDIM, HW, CDIM,
        0L, sAct, sAct, 1.f, out_b, nullptr, bufB);
}

// round 5
// speedup vs baseline: 3.5186x; 2.0181x over previous
#include <cuda_runtime.h>
#include <cuda_bf16.h>
#include <cstdint>
#include <cstddef>

#define BATCH 8
#define CDIM 256
#define HW 4096
#define TDIM 1024

// ---------------------------------------------------------------------------
// Static scratch (allocation forbidden)
// ---------------------------------------------------------------------------
__device__ float g_bufA[(size_t)BATCH * CDIM * HW];                  // 33.5 MB
__device__ float g_bufB[(size_t)BATCH * CDIM * HW];                  // 33.5 MB
__device__ float g_qkv [(size_t)BATCH * 3 * CDIM * HW];              // 100.6 MB
__device__ float g_sim [(size_t)BATCH * HW * HW];                    // 536 MB
__device__ float g_temb[BATCH * CDIM];
__device__ __nv_bfloat16 g_qT  [(size_t)BATCH * HW * CDIM];
__device__ __nv_bfloat16 g_kT  [(size_t)BATCH * HW * CDIM];
__device__ __nv_bfloat16 g_vbf [(size_t)BATCH * CDIM * HW];
__device__ __nv_bfloat16 g_attn[(size_t)BATCH * HW * HW];            // 268 MB
// tf32-rounded weights
__device__ float g_w1r[CDIM * CDIM * 9];
__device__ float g_w2r[CDIM * CDIM * 9];
__device__ float g_wqr[3 * CDIM * CDIM];
__device__ float g_wor[CDIM * CDIM];

// ---------------------------------------------------------------------------
// PTX helpers
// ---------------------------------------------------------------------------
__device__ __forceinline__ uint32_t smem_u32(const void* p) {
    uint32_t a;
    asm("{ .reg .u64 t; cvta.to.shared.u64 t, %1; cvt.u32.u64 %0, t; }"
        : "=r"(a) : "l"(p));
    return a;
}
__device__ __forceinline__ void cp16(uint32_t dst, const void* src) {
    asm volatile("cp.async.cg.shared.global [%0], [%1], 16;" :: "r"(dst), "l"(src));
}
__device__ __forceinline__ void cp4_pred(uint32_t dst, const void* src, bool p) {
    int sz = p ? 4 : 0;
    asm volatile("cp.async.ca.shared.global [%0], [%1], 4, %2;"
                 :: "r"(dst), "l"(src), "r"(sz));
}
#define CP_COMMIT() asm volatile("cp.async.commit_group;" ::: "memory")
#define CP_WAIT(n)  asm volatile("cp.async.wait_group %0;" :: "n"(n) : "memory")

__device__ __forceinline__ void ldsm4(uint32_t& r0, uint32_t& r1,
                                      uint32_t& r2, uint32_t& r3, uint32_t addr) {
    asm volatile("ldmatrix.sync.aligned.m8n8.x4.shared.b16 {%0,%1,%2,%3}, [%4];"
                 : "=r"(r0), "=r"(r1), "=r"(r2), "=r"(r3) : "r"(addr));
}
__device__ __forceinline__ void mma16816(float* c, const uint32_t* a,
                                         uint32_t b0, uint32_t b1) {
    asm volatile(
        "mma.sync.aligned.m16n8k16.row.col.f32.bf16.bf16.f32 "
        "{%0,%1,%2,%3}, {%4,%5,%6,%7}, {%8,%9}, {%0,%1,%2,%3};"
        : "+f"(c[0]), "+f"(c[1]), "+f"(c[2]), "+f"(c[3])
        : "r"(a[0]), "r"(a[1]), "r"(a[2]), "r"(a[3]), "r"(b0), "r"(b1));
}
__device__ __forceinline__ void mma1688_tf32(float* c, const uint32_t* a,
                                             uint32_t b0, uint32_t b1) {
    asm volatile(
        "mma.sync.aligned.m16n8k8.row.col.f32.tf32.tf32.f32 "
        "{%0,%1,%2,%3}, {%4,%5,%6,%7}, {%8,%9}, {%0,%1,%2,%3};"
        : "+f"(c[0]), "+f"(c[1]), "+f"(c[2]), "+f"(c[3])
        : "r"(a[0]), "r"(a[1]), "r"(a[2]), "r"(a[3]), "r"(b0), "r"(b1));
}
__device__ __forceinline__ float tf32r(float x) {
    uint32_t u;
    asm("cvt.rna.tf32.f32 %0, %1;" : "=r"(u) : "f"(x));
    return __uint_as_float(u);
}

// ---------------------------------------------------------------------------
// TF32 GEMM: C[m][n] = sum_k A[m][k]*B(k,n)  (+bias[m]) (+bias2[z*M+m]) (+res)
// A: [Mtot][K] fp32 (tf32-rounded), weights (no batch stride).
// BMODE 0: B global [K][4096] fp32 (tf32-rounded), batch stride sB.
// BMODE 1: implicit im2col 3x3 SAME over B = [256][64*64], K = 2304.
// CTA tile 128x128, BK=32, cp.async double buffer, 8 warps (4m x 2n).
// grid (32, Mtot/128, BATCH), 256 threads.
// ---------------------------------------------------------------------------
#define TF_APITCH 36
#define TF_BPITCH 132
#define TF_ASTG (128 * TF_APITCH * 4)           // 18432
#define TF_BSTG (32 * TF_BPITCH * 4)            // 16896
#define TF_STAGE (TF_ASTG + TF_BSTG)            // 35328
#define TF_SMEM (2 * TF_STAGE)                  // 70656

__device__ __forceinline__ void tf_stage_a(
    uint32_t sbA, const float* __restrict__ A, int K, int k0, int tid)
{
    #pragma unroll
    for (int i = 0; i < 4; i++) {
        const int v = tid + i * 256;
        const int r = v >> 3, sub = v & 7;
        cp16(sbA + (r * TF_APITCH + sub * 4) * 4, A + (size_t)r * K + k0 + sub * 4);
    }
}
__device__ __forceinline__ void tf_stage_kn(
    uint32_t sbB, const float* __restrict__ B, int k0, int bn, int tid)
{
    #pragma unroll
    for (int i = 0; i < 4; i++) {
        const int v = tid + i * 256;
        const int k = v >> 5, sub = v & 31;
        cp16(sbB + (k * TF_BPITCH + sub * 4) * 4,
             B + (size_t)(k0 + k) * 4096 + bn + sub * 4);
    }
}
__device__ __forceinline__ void tf_stage_conv(
    uint32_t sbB, const float* __restrict__ B, int k0, int bn, int tid)
{
    const int n = tid & 127, th = tid >> 7;
    const int nn = bn + n;
    const int y0 = nn >> 6, x0 = nn & 63;
    #pragma unroll
    for (int i = 0; i < 16; i++) {
        const int k = 2 * i + th;
        const int kk = k0 + k;
        const int ci = kk / 9;
        const int tap = kk - ci * 9;
        const int t3 = tap / 3;
        const int dy = t3 - 1, dx = tap - t3 * 3 - 1;
        const int y = y0 + dy, x = x0 + dx;
        const bool p = ((unsigned)x < 64u) && ((unsigned)y < 64u);
        cp4_pred(sbB + (k * TF_BPITCH + n) * 4, B + ci * 4096 + y * 64 + x, p);
    }
}

template<int BMODE>
__global__ __launch_bounds__(256, 2) void tf32_gemm_kernel(
    const float* __restrict__ A, const float* __restrict__ B, float* __restrict__ C,
    int M, int K, long sB, long sC,
    const float* __restrict__ bias, const float* __restrict__ bias2,
    const float* __restrict__ res)
{
    extern __shared__ char smem[];
    const uint32_t sb = smem_u32(smem);
    const int tid = threadIdx.x;
    const int wid = tid >> 5, lane = tid & 31;
    const int wm = wid & 3, wn = wid >> 2;
    const int z = blockIdx.z;
    const int bm = blockIdx.y * 128, bn = blockIdx.x * 128;
    A += (size_t)bm * K;
    B += (size_t)z * sB;
    C += (size_t)z * sC;
    const float* rp = res ? res + (size_t)z * sC : nullptr;

    float acc[2][8][4];
    #pragma unroll
    for (int mt = 0; mt < 2; mt++)
        #pragma unroll
        for (int nt = 0; nt < 8; nt++)
            #pragma unroll
            for (int e = 0; e < 4; e++) acc[mt][nt][e] = 0.f;

    const int S = K >> 5;
    tf_stage_a(sb, A, K, 0, tid);
    if (BMODE == 0) tf_stage_kn(sb + TF_ASTG, B, 0, bn, tid);
    else            tf_stage_conv(sb + TF_ASTG, B, 0, bn, tid);
    CP_COMMIT();

    for (int s = 0; s < S; s++) {
        if (s + 1 < S) {
            const uint32_t nb = sb + ((s + 1) & 1) * TF_STAGE;
            tf_stage_a(nb, A, K, (s + 1) << 5, tid);
            if (BMODE == 0) tf_stage_kn(nb + TF_ASTG, B, (s + 1) << 5, bn, tid);
            else            tf_stage_conv(nb + TF_ASTG, B, (s + 1) << 5, bn, tid);
            CP_COMMIT();
            CP_WAIT(1);
        } else {
            CP_WAIT(0);
        }
        __syncthreads();

        const float* cA = (const float*)(smem + (s & 1) * TF_STAGE);
        const float* cB = (const float*)(smem + (s & 1) * TF_STAGE + TF_ASTG);
        #pragma unroll
        for (int ks = 0; ks < 4; ks++) {
            const int kk = ks * 8;
            uint32_t a[2][4];
            #pragma unroll
            for (int mt = 0; mt < 2; mt++) {
                const int m = wm * 32 + mt * 16 + (lane >> 2);
                const float* p = cA + m * TF_APITCH + kk + (lane & 3);
                a[mt][0] = __float_as_uint(p[0]);
                a[mt][1] = __float_as_uint(p[8 * TF_APITCH]);
                a[mt][2] = __float_as_uint(p[4]);
                a[mt][3] = __float_as_uint(p[8 * TF_APITCH + 4]);
            }
            #pragma unroll
            for (int nt = 0; nt < 8; nt++) {
                const int n = wn * 64 + nt * 8 + (lane >> 2);
                const float* p = cB + (kk + (lane & 3)) * TF_BPITCH + n;
                const uint32_t b0 = __float_as_uint(p[0]);
                const uint32_t b1 = __float_as_uint(p[4 * TF_BPITCH]);
                mma1688_tf32(acc[0][nt], a[0], b0, b1);
                mma1688_tf32(acc[1][nt], a[1], b0, b1);
            }
        }
        __syncthreads();
    }

    #pragma unroll
    for (int mt = 0; mt < 2; mt++) {
        const int r0 = bm + wm * 32 + mt * 16 + (lane >> 2);
        float bb0 = 0.f, bb1 = 0.f;
        if (bias)  { bb0 = bias[r0]; bb1 = bias[r0 + 8]; }
        if (bias2) { bb0 += bias2[z * M + r0]; bb1 += bias2[z * M + r0 + 8]; }
        #pragma unroll
        for (int nt = 0; nt < 8; nt++) {
            const int col = bn + wn * 64 + nt * 8 + (lane & 3) * 2;
            const size_t o0 = (size_t)r0 * 4096 + col;
            const size_t o1 = o0 + (size_t)8 * 4096;
            float2 v0 = { acc[mt][nt][0] + bb0, acc[mt][nt][1] + bb0 };
            float2 v1 = { acc[mt][nt][2] + bb1, acc[mt][nt][3] + bb1 };
            if (rp) {
                float2 q0 = *(const float2*)(rp + o0);
                float2 q1 = *(const float2*)(rp + o1);
                v0.x += q0.x; v0.y += q0.y; v1.x += q1.x; v1.y += q1.y;
            }
            *(float2*)(C + o0) = v0;
            *(float2*)(C + o1) = v1;
        }
    }
}

// elementwise tf32 rounding (float4 granular)
__global__ __launch_bounds__(256) void tf32_round_kernel(
    const float* __restrict__ in, float* __restrict__ out, int n4)
{
    const int i = blockIdx.x * 256 + threadIdx.x;
    if (i < n4) {
        float4 v = ((const float4*)in)[i];
        v.x = tf32r(v.x); v.y = tf32r(v.y); v.z = tf32r(v.z); v.w = tf32r(v.w);
        ((float4*)out)[i] = v;
    }
}

// ---------------------------------------------------------------------------
// bf16 tensor-core GEMM (attention) — unchanged from R4
// ---------------------------------------------------------------------------
#define MMA_STAGE 20480

__device__ __forceinline__ void mma_load_stage(
    uint32_t sbase, const __nv_bfloat16* __restrict__ A,
    const __nv_bfloat16* __restrict__ B, int K, int k0, int tid)
{
    #pragma unroll
    for (int h = 0; h < 2; h++) {
        const int c = tid + h * 256;
        const int r = c >> 2, sub = c & 3;
        cp16(sbase + r * 80 + sub * 16, A + (size_t)r * K + k0 + sub * 8);
        cp16(sbase + 10240 + r * 80 + sub * 16, B + (size_t)r * K + k0 + sub * 8);
    }
}

__global__ __launch_bounds__(256, 2) void mma_gemm_kernel(
    const __nv_bfloat16* __restrict__ A, const __nv_bfloat16* __restrict__ B,
    float* __restrict__ C, int K, long sA, long sB, long sC, float alpha)
{
    __shared__ __align__(128) char smem[2 * MMA_STAGE];
    const uint32_t sb = smem_u32(smem);
    const int tid = threadIdx.x;
    const int wid = tid >> 5, lane = tid & 31;
    const int wm = wid & 3, wn = wid >> 2;
    const int z = blockIdx.z;
    const int bm = blockIdx.y * 128, bn = blockIdx.x * 128;
    A += (size_t)z * sA + (size_t)bm * K;
    B += (size_t)z * sB + (size_t)bn * K;
    C += (size_t)z * sC;

    float acc[2][8][4];
    #pragma unroll
    for (int mt = 0; mt < 2; mt++)
        #pragma unroll
        for (int nt = 0; nt < 8; nt++)
            #pragma unroll
            for (int e = 0; e < 4; e++) acc[mt][nt][e] = 0.f;

    const int NC = K >> 5;
    mma_load_stage(sb, A, B, K, 0, tid);
    CP_COMMIT();

    const int a_r  = lane & 15;
    const int a_kc = (lane >> 4) << 3;
    const int b_r  = (lane & 7) + ((lane >> 4) << 3);
    const int b_kc = ((lane >> 3) & 1) << 3;

    for (int c = 0; c < NC; c++) {
        if (c + 1 < NC) {
            mma_load_stage(sb + ((c + 1) & 1) * MMA_STAGE, A, B, K, (c + 1) << 5, tid);
            CP_COMMIT();
            CP_WAIT(1);
        } else {
            CP_WAIT(0);
        }
        __syncthreads();

        const uint32_t stA = sb + (c & 1) * MMA_STAGE;
        const uint32_t stB = stA + 10240;
        #pragma unroll
        for (int kk = 0; kk < 32; kk += 16) {
            uint32_t a[2][4];
            #pragma unroll
            for (int mt = 0; mt < 2; mt++) {
                const int r = wm * 32 + mt * 16 + a_r;
                ldsm4(a[mt][0], a[mt][1], a[mt][2], a[mt][3],
                      stA + r * 80 + (kk + a_kc) * 2);
            }
            uint32_t b[8][2];
            #pragma unroll
            for (int p = 0; p < 4; p++) {
                const int nr = wn * 64 + p * 16 + b_r;
                ldsm4(b[p * 2][0], b[p * 2][1], b[p * 2 + 1][0], b[p * 2 + 1][1],
                      stB + nr * 80 + (kk + b_kc) * 2);
            }
            #pragma unroll
            for (int mt = 0; mt < 2; mt++)
                #pragma unroll
                for (int nt = 0; nt < 8; nt++)
                    mma16816(acc[mt][nt], a[mt], b[nt][0], b[nt][1]);
        }
        __syncthreads();
    }

    #pragma unroll
    for (int mt = 0; mt < 2; mt++) {
        const int row0 = bm + wm * 32 + mt * 16 + (lane >> 2);
        #pragma unroll
        for (int nt = 0; nt < 8; nt++) {
            const int col = bn + wn * 64 + nt * 8 + (lane & 3) * 2;
            float2 v0 = { acc[mt][nt][0] * alpha, acc[mt][nt][1] * alpha };
            float2 v1 = { acc[mt][nt][2] * alpha, acc[mt][nt][3] * alpha };
            *(float2*)(C + (size_t)row0 * 4096 + col) = v0;
            *(float2*)(C + (size_t)(row0 + 8) * 4096 + col) = v1;
        }
    }
}

// ---------------------------------------------------------------------------
// Transpose+convert: q,k fp32 [C][HW] -> bf16 [HW][C]
// ---------------------------------------------------------------------------
__global__ __launch_bounds__(256) void transpose_cvt_kernel(
    const float* __restrict__ qkv, __nv_bfloat16* __restrict__ qT,
    __nv_bfloat16* __restrict__ kT)
{
    __shared__ float tile[32][33];
    const int b = blockIdx.z >> 1, which = blockIdx.z & 1;
    const float* s = qkv + (size_t)b * (3 * CDIM * HW)
                   + (size_t)(which * CDIM + blockIdx.y * 32) * HW + blockIdx.x * 32;
    __nv_bfloat16* d = (which ? kT : qT) + (size_t)b * HW * CDIM
                     + (size_t)(blockIdx.x * 32) * CDIM + blockIdx.y * 32;
    const int tx = threadIdx.x & 31, ty = threadIdx.x >> 5;
    #pragma unroll
    for (int r = 0; r < 32; r += 8)
        tile[ty + r][tx] = s[(size_t)(ty + r) * HW + tx];
    __syncthreads();
    #pragma unroll
    for (int r = 0; r < 32; r += 8)
        d[(size_t)(ty + r) * CDIM + tx] = __float2bfloat16(tile[tx][ty + r]);
}

__global__ __launch_bounds__(256) void cvt_v_kernel(
    const float* __restrict__ qkv, __nv_bfloat16* __restrict__ v)
{
    const size_t i = (size_t)blockIdx.x * 1024 + threadIdx.x * 4;
    const size_t z = blockIdx.y;
    float4 f = *(const float4*)(qkv + z * (size_t)(3 * CDIM * HW)
                                + (size_t)2 * CDIM * HW + i);
    __nv_bfloat162 lo = __floats2bfloat162_rn(f.x, f.y);
    __nv_bfloat162 hi = __floats2bfloat162_rn(f.z, f.w);
    uint2 o = { *(uint32_t*)&lo, *(uint32_t*)&hi };
    *(uint2*)(v + z * (size_t)(CDIM * HW) + i) = o;
}

// ---------------------------------------------------------------------------
// GroupNorm (+ optional SiLU, + optional tf32 output rounding)
// ---------------------------------------------------------------------------
__global__ __launch_bounds__(256) void groupnorm_kernel(
    const float* __restrict__ in, float* __restrict__ out,
    const float* __restrict__ sc, const float* __restrict__ bi,
    int do_silu, int do_round)
{
    __shared__ float s_sum[256], s_sq[256];
    __shared__ float s_stats[2];
    const int t = threadIdx.x;
    const int bg = blockIdx.x;
    const size_t base = (size_t)bg * 32768;
    const int g = bg & 31;

    float sum = 0.f, sq = 0.f;
    for (int i = t * 4; i < 32768; i += 1024) {
        float4 v = *(const float4*)&in[base + i];
        sum += v.x + v.y + v.z + v.w;
        sq  += v.x*v.x + v.y*v.y + v.z*v.z + v.w*v.w;
    }
    s_sum[t] = sum; s_sq[t] = sq;
    __syncthreads();
    for (int s = 128; s > 0; s >>= 1) {
        if (t < s) { s_sum[t] += s_sum[t + s]; s_sq[t] += s_sq[t + s]; }
        __syncthreads();
    }
    if (t == 0) {
        float mean = s_sum[0] * (1.f / 32768.f);
        float var  = s_sq[0] * (1.f / 32768.f) - mean * mean;
        s_stats[0] = mean;
        s_stats[1] = rsqrtf(var + 1e-5f);
    }
    __syncthreads();
    const float mean = s_stats[0], rstd = s_stats[1];

    for (int i = t * 4; i < 32768; i += 1024) {
        const int c = (g << 3) + (i >> 12);
        const float a = sc[c] * rstd;
        const float b2 = bi[c] - mean * a;
        float4 v = *(const float4*)&in[base + i];
        float4 o;
        o.x = v.x * a + b2; o.y = v.y * a + b2;
        o.z = v.z * a + b2; o.w = v.w * a + b2;
        if (do_silu) {
            o.x = o.x / (1.f + __expf(-o.x));
            o.y = o.y / (1.f + __expf(-o.y));
            o.z = o.z / (1.f + __expf(-o.z));
            o.w = o.w / (1.f + __expf(-o.w));
        }
        if (do_round) {
            o.x = tf32r(o.x); o.y = tf32r(o.y);
            o.z = tf32r(o.z); o.w = tf32r(o.w);
        }
        *(float4*)&out[base + i] = o;
    }
}

// ---------------------------------------------------------------------------
// time-MLP
// ---------------------------------------------------------------------------
__global__ __launch_bounds__(256) void mlp_kernel(
    const float* __restrict__ te, const float* __restrict__ w,
    const float* __restrict__ mb, float* __restrict__ temb)
{
    __shared__ float s[TDIM];
    const int b = blockIdx.x, t = threadIdx.x;
    for (int i = t; i < TDIM; i += 256) {
        float v = te[b * TDIM + i];
        s[i] = v / (1.f + __expf(-v));
    }
    __syncthreads();
    float acc = 0.f;
    for (int k = 0; k < TDIM; k++) acc = fmaf(s[k], w[k * CDIM + t], acc);
    temb[b * CDIM + t] = acc + mb[t];
}

// ---------------------------------------------------------------------------
// Row softmax: fp32 sim in, bf16 attn out.
// ---------------------------------------------------------------------------
__global__ __launch_bounds__(256) void softmax_kernel(
    const float* __restrict__ sim, __nv_bfloat16* __restrict__ attn)
{
    __shared__ float red[256];
    const int t = threadIdx.x;
    const float4* p = (const float4*)(sim + (size_t)blockIdx.x * HW);
    __nv_bfloat16* arow = attn + (size_t)blockIdx.x * HW;

    float4 v[4];
    float mx = -1e30f;
    #pragma unroll
    for (int j = 0; j < 4; j++) {
        v[j] = p[t + j * 256];
        mx = fmaxf(mx, fmaxf(fmaxf(v[j].x, v[j].y), fmaxf(v[j].z, v[j].w)));
    }
    red[t] = mx; __syncthreads();
    for (int s = 128; s > 0; s >>= 1) {
        if (t < s) red[t] = fmaxf(red[t], red[t + s]);
        __syncthreads();
    }
    mx = red[0];
    __syncthreads();

    float sum = 0.f;
    #pragma unroll
    for (int j = 0; j < 4; j++) {
        v[j].x = __expf(v[j].x - mx); v[j].y = __expf(v[j].y - mx);
        v[j].z = __expf(v[j].z - mx); v[j].w = __expf(v[j].w - mx);
        sum += v[j].x + v[j].y + v[j].z + v[j].w;
    }
    red[t] = sum; __syncthreads();
    for (int s = 128; s > 0; s >>= 1) {
        if (t < s) red[t] += red[t + s];
        __syncthreads();
    }
    const float inv = 1.f / red[0];
    #pragma unroll
    for (int j = 0; j < 4; j++) {
        __nv_bfloat162 lo = __floats2bfloat162_rn(v[j].x * inv, v[j].y * inv);
        __nv_bfloat162 hi = __floats2bfloat162_rn(v[j].z * inv, v[j].w * inv);
        uint2 o = { *(uint32_t*)&lo, *(uint32_t*)&hi };
        *(uint2*)(arow + (size_t)(t + j * 256) * 4) = o;
    }
}

// ---------------------------------------------------------------------------
// Launch
// ---------------------------------------------------------------------------
extern "C" void kernel_launch(void* const* d_in, const int* in_sizes, int n_in,
                              void* d_out, int out_size)
{
    const float* x        = (const float*)d_in[0];
    const float* time_emb = (const float*)d_in[1];
    const float* gn1_s    = (const float*)d_in[2];
    const float* gn1_b    = (const float*)d_in[3];
    const float* conv1_w  = (const float*)d_in[4];
    const float* conv1_b  = (const float*)d_in[5];
    const float* mlp_w    = (const float*)d_in[6];
    const float* mlp_b    = (const float*)d_in[7];
    const float* gn2_s    = (const float*)d_in[8];
    const float* gn2_b    = (const float*)d_in[9];
    const float* conv2_w  = (const float*)d_in[10];
    const float* conv2_b  = (const float*)d_in[11];
    const float* an_s     = (const float*)d_in[12];
    const float* an_b     = (const float*)d_in[13];
    const float* qkv_w    = (const float*)d_in[14];
    const float* qkv_b    = (const float*)d_in[15];
    const float* out_w    = (const float*)d_in[16];
    const float* out_b    = (const float*)d_in[17];
    float* out = (float*)d_out;

    float *bufA, *bufB, *qkvb, *sim, *temb, *w1r, *w2r, *wqr, *wor;
    __nv_bfloat16 *qT, *kT, *vbf, *attn;
    cudaGetSymbolAddress((void**)&bufA, g_bufA);
    cudaGetSymbolAddress((void**)&bufB, g_bufB);
    cudaGetSymbolAddress((void**)&qkvb, g_qkv);
    cudaGetSymbolAddress((void**)&sim,  g_sim);
    cudaGetSymbolAddress((void**)&temb, g_temb);
    cudaGetSymbolAddress((void**)&w1r,  g_w1r);
    cudaGetSymbolAddress((void**)&w2r,  g_w2r);
    cudaGetSymbolAddress((void**)&wqr,  g_wqr);
    cudaGetSymbolAddress((void**)&wor,  g_wor);
    cudaGetSymbolAddress((void**)&qT,   g_qT);
    cudaGetSymbolAddress((void**)&kT,   g_kT);
    cudaGetSymbolAddress((void**)&vbf,  g_vbf);
    cudaGetSymbolAddress((void**)&attn, g_attn);

    cudaFuncSetAttribute(tf32_gemm_kernel<0>,
                         cudaFuncAttributeMaxDynamicSharedMemorySize, TF_SMEM);
    cudaFuncSetAttribute(tf32_gemm_kernel<1>,
                         cudaFuncAttributeMaxDynamicSharedMemorySize, TF_SMEM);

    const long sAct = (long)CDIM * HW;
    const long sQkv = (long)3 * CDIM * HW;
    const long sSim = (long)HW * HW;

    // tf32-round the weights
    tf32_round_kernel<<<576, 256>>>(conv1_w, w1r, CDIM * CDIM * 9 / 4);
    tf32_round_kernel<<<576, 256>>>(conv2_w, w2r, CDIM * CDIM * 9 / 4);
    tf32_round_kernel<<<192, 256>>>(qkv_w, wqr, 3 * CDIM * CDIM / 4);
    tf32_round_kernel<<<64, 256>>>(out_w, wor, CDIM * CDIM / 4);

    mlp_kernel<<<BATCH, 256>>>(time_emb, mlp_w, mlp_b, temb);

    // t1 = silu(gn1(x)) [tf32-rounded]
    groupnorm_kernel<<<BATCH * 32, 256>>>(x, bufA, gn1_s, gn1_b, 1, 1);
    // h1 = conv1(t1) + b + temb
    tf32_gemm_kernel<1><<<dim3(32, 2, BATCH), 256, TF_SMEM>>>(
        w1r, bufA, bufB, CDIM, CDIM * 9, sAct, sAct, conv1_b, temb, nullptr);
    // t2 = silu(gn2(h1)) [tf32-rounded]
    groupnorm_kernel<<<BATCH * 32, 256>>>(bufB, bufA, gn2_s, gn2_b, 1, 1);
    // xr = conv2(t2) + b + x
    tf32_gemm_kernel<1><<<dim3(32, 2, BATCH), 256, TF_SMEM>>>(
        w2r, bufA, bufB, CDIM, CDIM * 9, sAct, sAct, conv2_b, nullptr, x);
    // a = gn_an(xr) [tf32-rounded]
    groupnorm_kernel<<<BATCH * 32, 256>>>(bufB, bufA, an_s, an_b, 0, 1);
    // qkv = W_qkv @ a + b
    tf32_gemm_kernel<0><<<dim3(32, 6, BATCH), 256, TF_SMEM>>>(
        wqr, bufA, qkvb, 3 * CDIM, CDIM, sAct, sQkv, qkv_b, nullptr, nullptr);

    // bf16 prep
    transpose_cvt_kernel<<<dim3(HW / 32, CDIM / 32, BATCH * 2), 256>>>(qkvb, qT, kT);
    cvt_v_kernel<<<dim3(1024, BATCH), 256>>>(qkvb, vbf);

    // sim = (Q^T K) * C^-0.5   [bf16 mma]
    mma_gemm_kernel<<<dim3(32, 32, BATCH), 256>>>(
        qT, kT, sim, CDIM, (long)HW * CDIM, (long)HW * CDIM, sSim, 0.0625f);
    // softmax -> bf16 attn
    softmax_kernel<<<BATCH * HW, 256>>>(sim, attn);
    // o = V attn^T  [bf16 mma] -> bufA
    mma_gemm_kernel<<<dim3(32, 2, BATCH), 256>>>(
        vbf, attn, bufA, HW, sAct, sSim, sAct, 1.f);

    // round o to tf32 (in place), then out = W_out @ o + b + xr
    tf32_round_kernel<<<32768, 256>>>(bufA, bufA, (int)(BATCH * sAct / 4));
    tf32_gemm_kernel<0><<<dim3(32, 2, BATCH), 256, TF_SMEM>>>(
        wor, bufA, out, CDIM, CDIM, sAct, sAct, out_b, nullptr, bufB);
}